// round 5
// baseline (speedup 1.0000x reference)
#include <cuda_runtime.h>
#include <math.h>

// AfmoeTokenChoiceRouter — round 1 baseline
// logits = x @ W^T  (T=16384, H=2048, E=64), sigmoid, biased top-8, norm, *2.5
// Output layout: [ top_scores (T*8 f32) | selected_experts as f32 (T*8) ]

#define TPB        256     // threads per block
#define TOK_BLK    64      // tokens per block
#define KC         32      // K chunk
#define PAD_A      66      // 264B rows: 8B-aligned for float2
#define PAD_B      68      // 272B rows: 16B-aligned for float4
#define TOPK       8
#define ROUTE_SCALE 2.5f

__device__ __forceinline__ unsigned long long pack2(float lo, float hi) {
    unsigned long long r;
    asm("mov.b64 %0, {%1, %2};" : "=l"(r) : "f"(lo), "f"(hi));
    return r;
}
__device__ __forceinline__ void unpack2(float& lo, float& hi, unsigned long long v) {
    asm("mov.b64 {%0, %1}, %2;" : "=f"(lo), "=f"(hi) : "l"(v));
}
__device__ __forceinline__ void fma2(unsigned long long& d, unsigned long long a, unsigned long long b) {
    asm("fma.rn.f32x2 %0, %1, %2, %3;" : "=l"(d) : "l"(a), "l"(b), "l"(d));
}

__global__ __launch_bounds__(TPB, 2)
void afmoe_router_kernel(const float* __restrict__ x,      // [T, H]
                         const float* __restrict__ bias,   // [E]  (E==64)
                         const float* __restrict__ w,      // [E, H]
                         float* __restrict__ out,          // [2*T*8]
                         int T, int H)
{
    __shared__ float As[KC][PAD_A];      // As[h][tok]
    __shared__ float Bs[KC][PAD_B];      // Bs[h][exp]
    __shared__ float Sc[TOK_BLK][65];    // sigmoid scores [tok][exp]
    __shared__ float Sb[64];             // expert bias

    const int tid  = threadIdx.x;
    const int tx   = tid & 15;           // expert micro-tile (4 experts)
    const int ty   = tid >> 4;           // token micro-tile (4 tokens)
    const int tok0 = blockIdx.x * TOK_BLK;

    if (tid < 64) Sb[tid] = bias[tid];

    // 8 packed accumulators: 2 token-pairs x 4 experts
    unsigned long long acc[2][4];
    #pragma unroll
    for (int p = 0; p < 2; p++)
        #pragma unroll
        for (int e = 0; e < 4; e++) acc[p][e] = 0ULL;

    const int nChunks = H / KC;
    for (int kb = 0; kb < nChunks; kb++) {
        const int hbase = kb * KC;
        // Load A tile: 64 tokens x 32 h. Each warp = 1 token's 32 h (coalesced 128B).
        #pragma unroll
        for (int j = 0; j < (TOK_BLK * KC) / TPB; j++) {
            int idx = tid + j * TPB;
            int tk  = idx >> 5;          // 0..63
            int h   = idx & 31;
            int gt  = tok0 + tk;
            As[h][tk] = (gt < T) ? x[(size_t)gt * H + hbase + h] : 0.0f;
        }
        // Load B tile: 64 experts x 32 h.
        #pragma unroll
        for (int j = 0; j < (64 * KC) / TPB; j++) {
            int idx = tid + j * TPB;
            int e   = idx >> 5;
            int h   = idx & 31;
            Bs[h][e] = w[(size_t)e * H + hbase + h];
        }
        __syncthreads();

        #pragma unroll
        for (int kk = 0; kk < KC; kk++) {
            const float2 a0 = *(const float2*)&As[kk][ty * 4];
            const float2 a1 = *(const float2*)&As[kk][ty * 4 + 2];
            const float4 bq = *(const float4*)&Bs[kk][tx * 4];
            unsigned long long ap0 = pack2(a0.x, a0.y);
            unsigned long long ap1 = pack2(a1.x, a1.y);
            unsigned long long b0  = pack2(bq.x, bq.x);
            unsigned long long b1  = pack2(bq.y, bq.y);
            unsigned long long b2  = pack2(bq.z, bq.z);
            unsigned long long b3  = pack2(bq.w, bq.w);
            fma2(acc[0][0], ap0, b0); fma2(acc[0][1], ap0, b1);
            fma2(acc[0][2], ap0, b2); fma2(acc[0][3], ap0, b3);
            fma2(acc[1][0], ap1, b0); fma2(acc[1][1], ap1, b1);
            fma2(acc[1][2], ap1, b2); fma2(acc[1][3], ap1, b3);
        }
        __syncthreads();
    }

    // Sigmoid -> shared score tile
    #pragma unroll
    for (int p = 0; p < 2; p++) {
        #pragma unroll
        for (int e = 0; e < 4; e++) {
            float lo, hi;
            unpack2(lo, hi, acc[p][e]);
            Sc[ty * 4 + 2 * p    ][tx * 4 + e] = 1.0f / (1.0f + expf(-lo));
            Sc[ty * 4 + 2 * p + 1][tx * 4 + e] = 1.0f / (1.0f + expf(-hi));
        }
    }
    __syncthreads();

    // Top-8 per token: one warp handles 8 tokens serially.
    const int warp = tid >> 5;
    const int lane = tid & 31;
    const unsigned FULL = 0xFFFFFFFFu;

    for (int t = 0; t < 8; t++) {
        const int tl = warp * 8 + t;         // local token 0..63
        const int gt = tok0 + tl;
        const int e0 = lane, e1 = lane + 32;
        const float s0 = Sc[tl][e0];
        const float s1 = Sc[tl][e1];
        float b0v = s0 + Sb[e0];
        float b1v = s1 + Sb[e1];

        float myval = 0.0f;                  // this lane's (i==lane) selected score
        int   myidx = 0;
        float ssum  = 0.0f;

        #pragma unroll
        for (int i = 0; i < TOPK; i++) {
            // lane-local best (tie -> lower index: e0 < e1, so >= keeps e0)
            float v; int idx;
            if (b0v >= b1v) { v = b0v; idx = e0; }
            else            { v = b1v; idx = e1; }
            // warp reduce, tie -> lower index
            #pragma unroll
            for (int off = 16; off > 0; off >>= 1) {
                float ov  = __shfl_xor_sync(FULL, v, off);
                int   oid = __shfl_xor_sync(FULL, idx, off);
                if (ov > v || (ov == v && oid < idx)) { v = ov; idx = oid; }
            }
            // winner's unbiased sigmoid score (broadcast via smem)
            float sc = Sc[tl][idx];
            ssum += sc;
            if (lane == i) { myval = sc; myidx = idx; }
            // mask winner
            if (idx == e0) b0v = -INFINITY;
            if (idx == e1) b1v = -INFINITY;
        }

        const float scale = ROUTE_SCALE / (ssum + 1e-20f);
        if (lane < TOPK && gt < T) {
            out[(size_t)gt * TOPK + lane]                    = myval * scale;
            out[(size_t)T * TOPK + (size_t)gt * TOPK + lane] = (float)myidx;
        }
    }
}

extern "C" void kernel_launch(void* const* d_in, const int* in_sizes, int n_in,
                              void* d_out, int out_size)
{
    const float* x    = (const float*)d_in[0];   // hidden_states [B*S*H]
    const float* bias = (const float*)d_in[1];   // expert_bias [E]
    const float* w    = (const float*)d_in[2];   // gate_w [E*H]

    const int E = in_sizes[1];                   // 64
    const int H = in_sizes[2] / E;               // 2048
    const int T = in_sizes[0] / H;               // 16384

    float* out = (float*)d_out;
    const int grid = (T + TOK_BLK - 1) / TOK_BLK;
    afmoe_router_kernel<<<grid, TPB>>>(x, bias, w, out, T, H);
}